// round 14
// baseline (speedup 1.0000x reference)
#include <cuda_runtime.h>

#define BH    16
#define LQ    512
#define LK    512
#define DD    64
#define TQ    16
#define TK    128
#define WPD   68     // smem row stride in floats: 272B, 16B-aligned, LDS.128 conflict-free

// Projected tensors, f32 [row][64]:
//   g_Wq[row][d] =  exp(2*wq)   (wq = Q@W1 + b1)
//   g_Wk[row][d] = -exp(2*wk)   (wk = K@W2 + b2)
__device__ float g_Wq[BH * LQ * DD];
__device__ float g_Wk[BH * LK * DD];

// ---------------------------------------------------------------------------
// Packed helpers
// ---------------------------------------------------------------------------
__device__ __forceinline__ double f2x2(float lo, float hi) {
    double r; asm("mov.b64 %0, {%1, %2};" : "=d"(r) : "f"(lo), "f"(hi)); return r;
}
__device__ __forceinline__ void unpack2(double p, float& lo, float& hi) {
    asm("mov.b64 {%0, %1}, %2;" : "=f"(lo), "=f"(hi) : "d"(p));
}
__device__ __forceinline__ double fmx2(double a, double b, double c) {
    double r; asm("fma.rn.f32x2 %0, %1, %2, %3;" : "=d"(r) : "d"(a), "d"(b), "d"(c)); return r;
}
// Reciprocal seed of +D from bits of (-D): 0xFEF311C3 - bits(-D). D > 0.
__device__ __forceinline__ double rcp_seed_from_neg(double dn) {
    unsigned lo, hi;
    asm("mov.b64 {%0, %1}, %2;" : "=r"(lo), "=r"(hi) : "d"(dn));
    lo = 0xFEF311C3u - lo;
    hi = 0xFEF311C3u - hi;
    double r; asm("mov.b64 %0, {%1, %2};" : "=d"(r) : "r"(lo), "r"(hi)); return r;
}

// ---------------------------------------------------------------------------
// Fused projection kernel (fp32, packed f32x2 inner loop).
//   blocks [0,256):    out =  exp(2*(Q*W1 + b1))
//   blocks [256,512):  out = -exp(2*(K*W2 + b2))
// ---------------------------------------------------------------------------
__global__ __launch_bounds__(256) void proj_fused_kernel(
    const float* __restrict__ Q, const float* __restrict__ K,
    const float* __restrict__ W1, const float* __restrict__ b1,
    const float* __restrict__ W2, const float* __restrict__ b2)
{
    __shared__ __align__(16) float Ws[DD][DD];
    __shared__ float Xs[32][DD + 1];

    const int  tid  = threadIdx.x;
    const bool isK  = (blockIdx.x >= 256);
    const int  blk  = isK ? (blockIdx.x - 256) : blockIdx.x;
    const int  rowBase = blk * 32;

    const float* __restrict__ X  = isK ? K  : Q;
    const float* __restrict__ W  = isK ? W2 : W1;
    const float* __restrict__ bb = isK ? b2 : b1;
    float* __restrict__ Out      = isK ? g_Wk : g_Wq;

    {
        const float4* src = (const float4*)W;
        float4* dst = (float4*)&Ws[0][0];
#pragma unroll
        for (int t = 0; t < 4; t++) dst[tid + t * 256] = src[tid + t * 256];
    }
#pragma unroll
    for (int t = 0; t < 8; t++) {
        int i = tid + t * 256;
        int r = i >> 6, c = i & 63;
        Xs[r][c] = X[(size_t)(rowBase + r) * DD + c];
    }
    __syncthreads();

    const int lane = tid & 31;
    const int eg   = tid >> 5;    // e-group: e = eg*8 + j

    double accp[4];               // packed f32 pairs
#pragma unroll
    for (int n = 0; n < 4; n++)
        accp[n] = f2x2(__ldg(&bb[eg * 8 + 2 * n]), __ldg(&bb[eg * 8 + 2 * n + 1]));

#pragma unroll
    for (int d = 0; d < DD; d++) {
        const float xv = Xs[lane][d];
        const double xvp = f2x2(xv, xv);
        const double2 wA = *(const double2*)&Ws[d][eg * 8];
        const double2 wB = *(const double2*)&Ws[d][eg * 8 + 4];
        accp[0] = fmx2(xvp, wA.x, accp[0]);
        accp[1] = fmx2(xvp, wA.y, accp[1]);
        accp[2] = fmx2(xvp, wB.x, accp[2]);
        accp[3] = fmx2(xvp, wB.y, accp[3]);
    }

    float acc[8];
#pragma unroll
    for (int n = 0; n < 4; n++) unpack2(accp[n], acc[2 * n], acc[2 * n + 1]);

    // exp transform, all columns: +exp(2x) for Q, -exp(2x) for K
    {
        const float sgn = isK ? -1.0f : 1.0f;
#pragma unroll
        for (int j = 0; j < 8; j++) acc[j] = sgn * __expf(2.0f * acc[j]);
    }

    __syncthreads();
#pragma unroll
    for (int j = 0; j < 8; j++) Xs[lane][eg * 8 + j] = acc[j];
    __syncthreads();
#pragma unroll
    for (int t = 0; t < 8; t++) {
        int i = tid + t * 256;
        int r = i >> 6, c = i & 63;
        Out[(size_t)(rowBase + r) * DD + c] = Xs[r][c];     // coalesced
    }
}

// ---------------------------------------------------------------------------
// Main kernel: 128-thread blocks, tile 16q x 128k, 4x4 micro-tile per warp,
// 5 CTAs/SM. ALL 64 d's via the exp-product form, ZERO inner-loop MUFU:
//   tanh(wq+wk) = 1 - 2/(1 + eq*ek), the 1 folds into the bias.
//   Per d-pair (packed f32x2): nden = fma(eq,nek,-1); magic seed (ALU);
//   Halley refine (h=fma(nden,r,1), t=fma(h,h,h), r'=fma(r,t,r), err e->e^3);
//   acc = fma(r', -2v, acc).  => 5 FMA-pipe ops / 2 elements.
// ---------------------------------------------------------------------------
__global__ __launch_bounds__(128, 5) void attn_main_kernel(
    const float* __restrict__ Vv, const float* __restrict__ bV,
    float* __restrict__ out)
{
    __shared__ __align__(16) float wq_s[TQ][WPD];    // 16 x 68 (eq)
    __shared__ __align__(16) float wk_s[TK][WPD];    // 128 x 68 (nek)
    __shared__ __align__(16) float v_s[DD];          // -2*v

    const int bh    = blockIdx.z;
    const int qBase = blockIdx.y * TQ;
    const int kBase = blockIdx.x * TK;
    const int tid   = threadIdx.x;

    // ---- fill smem (coalesced global reads, padded stores) ----
    {
        const float* src = g_Wq + (size_t)(bh * LQ + qBase) * DD;
#pragma unroll
        for (int t = 0; t < 8; t++) {                 // 1024 = 16*64
            int i = tid + t * 128;
            wq_s[i >> 6][i & 63] = src[i];
        }
    }
    {
        const float* src = g_Wk + (size_t)(bh * LK + kBase) * DD;
#pragma unroll
        for (int t = 0; t < 64; t++) {                // 8192 = 128*64
            int i = tid + t * 128;
            wk_s[i >> 6][i & 63] = src[i];
        }
    }
    if (tid < DD) v_s[tid] = -2.0f * Vv[tid];
    __syncthreads();

    const int ty = tid >> 5;          // warp id (0..3) -> q rows ty*4 .. ty*4+3
    const int tx = tid & 31;          // k lane; k = j*32 + tx

    double acc[4][4];
#pragma unroll
    for (int i = 0; i < 4; i++)
#pragma unroll
        for (int j = 0; j < 4; j++) acc[i][j] = 0.0;

    const double ONE  = f2x2(1.0f, 1.0f);
    const double MONE = f2x2(-1.0f, -1.0f);

    // ======== 16 iterations x 4 d's (2 packed pairs) ========
#pragma unroll 1
    for (int s2 = 0; s2 < 16; s2++) {
        const int c = 4 * s2;

        const double2 m2v2 = *(const double2*)&v_s[c];   // (-2v) pairs

        // nek pairs for 4 k's: LDS.128, stride 68 -> conflict-free
        double2 nek2[4];
#pragma unroll
        for (int j = 0; j < 4; j++)
            nek2[j] = *(const double2*)&wk_s[j * 32 + tx][c];

#pragma unroll
        for (int i = 0; i < 4; i++) {
            const double2 eq2 = *(const double2*)&wq_s[ty * 4 + i][c];  // broadcast

#pragma unroll
            for (int j = 0; j < 4; j++) {
                double nden0 = fmx2(eq2.x, nek2[j].x, MONE);   // -(1 + eq*ek)
                double nden1 = fmx2(eq2.y, nek2[j].y, MONE);
                double r0 = rcp_seed_from_neg(nden0);          // ~1/(1+p), ALU
                double r1 = rcp_seed_from_neg(nden1);
                double h0 = fmx2(nden0, r0, ONE);              // residual e
                double h1 = fmx2(nden1, r1, ONE);
                double t0 = fmx2(h0, h0, h0);                  // e + e^2
                double t1 = fmx2(h1, h1, h1);
                r0 = fmx2(r0, t0, r0);                         // Halley: err e^3
                r1 = fmx2(r1, t1, r1);
                acc[i][j] = fmx2(r0, m2v2.x, acc[i][j]);       // += (-2v)/(1+p)
                acc[i][j] = fmx2(r1, m2v2.y, acc[i][j]);
            }
        }
    }

    // ---- epilogue: bias + sum(v)  (v = -0.5 * stored -2v) ----
    float vsum = 0.0f;
#pragma unroll
    for (int c = 0; c < DD; c++) vsum += v_s[c];
    const float bv = bV[0] - 0.5f * vsum;

#pragma unroll
    for (int i = 0; i < 4; i++) {
        const size_t rowOff = (size_t)(bh * LQ + qBase + ty * 4 + i) * LK + kBase;
#pragma unroll
        for (int j = 0; j < 4; j++) {
            float lo, hi;
            unpack2(acc[i][j], lo, hi);
            out[rowOff + j * 32 + tx] = lo + hi + bv;      // coalesced
        }
    }
}

// ---------------------------------------------------------------------------
// Launch
// ---------------------------------------------------------------------------
extern "C" void kernel_launch(void* const* d_in, const int* in_sizes, int n_in,
                              void* d_out, int out_size)
{
    const float* Q  = (const float*)d_in[0];
    const float* K  = (const float*)d_in[1];
    const float* W1 = (const float*)d_in[2];
    const float* b1 = (const float*)d_in[3];
    const float* W2 = (const float*)d_in[4];
    const float* b2 = (const float*)d_in[5];
    const float* V  = (const float*)d_in[6];
    const float* bV = (const float*)d_in[7];
    float* out = (float*)d_out;

    proj_fused_kernel<<<512, 256>>>(Q, K, W1, b1, W2, b2);

    dim3 grid(LK / TK, LQ / TQ, BH);                  // 4 x 32 x 16 = 2048
    attn_main_kernel<<<grid, 128>>>(V, bV, out);
}

// round 15
// speedup vs baseline: 1.0657x; 1.0657x over previous
#include <cuda_runtime.h>

#define BH    16
#define LQ    512
#define LK    512
#define DD    64
#define DMUFU 44     // d in [0,44): raw values, MUFU tanh path
#define TQ    16
#define TK    128
#define WPD   68     // smem row stride in floats: 272B, 16B-aligned, LDS.128 conflict-free

// Projected tensors, f32 [row][64]:
//   g_Wq: cols 0..43 = raw wq,  cols 44..63 = exp(2*wq)
//   g_Wk: cols 0..43 = raw wk,  cols 44..63 = -exp(2*wk)
__device__ float g_Wq[BH * LQ * DD];
__device__ float g_Wk[BH * LK * DD];

// ---------------------------------------------------------------------------
// Helpers
// ---------------------------------------------------------------------------
__device__ __forceinline__ float tanhapx(float x) {
    float y; asm("tanh.approx.f32 %0, %1;" : "=f"(y) : "f"(x)); return y;
}
__device__ __forceinline__ double f2x2(float lo, float hi) {
    double r; asm("mov.b64 %0, {%1, %2};" : "=d"(r) : "f"(lo), "f"(hi)); return r;
}
__device__ __forceinline__ void unpack2(double p, float& lo, float& hi) {
    asm("mov.b64 {%0, %1}, %2;" : "=f"(lo), "=f"(hi) : "d"(p));
}
__device__ __forceinline__ double addx2(double a, double b) {
    double r; asm("add.rn.f32x2 %0, %1, %2;" : "=d"(r) : "d"(a), "d"(b)); return r;
}
__device__ __forceinline__ double fmx2(double a, double b, double c) {
    double r; asm("fma.rn.f32x2 %0, %1, %2, %3;" : "=d"(r) : "d"(a), "d"(b), "d"(c)); return r;
}
// Reciprocal seed of +D from bits of (-D): 0xFEF311C3 - bits(-D). D > 0.
__device__ __forceinline__ double rcp_seed_from_neg(double dn) {
    unsigned lo, hi;
    asm("mov.b64 {%0, %1}, %2;" : "=r"(lo), "=r"(hi) : "d"(dn));
    lo = 0xFEF311C3u - lo;
    hi = 0xFEF311C3u - hi;
    double r; asm("mov.b64 %0, {%1, %2};" : "=d"(r) : "r"(lo), "r"(hi)); return r;
}

// ---------------------------------------------------------------------------
// Fused projection kernel (fp32, packed f32x2 inner loop).
//   blocks [0,256):    Wq = Q*W1 + b1 ; cols 44..63 -> exp(2x)
//   blocks [256,512):  Wk = K*W2 + b2 ; cols 44..63 -> -exp(2x)
// ---------------------------------------------------------------------------
__global__ __launch_bounds__(256) void proj_fused_kernel(
    const float* __restrict__ Q, const float* __restrict__ K,
    const float* __restrict__ W1, const float* __restrict__ b1,
    const float* __restrict__ W2, const float* __restrict__ b2)
{
    __shared__ __align__(16) float Ws[DD][DD];
    __shared__ float Xs[32][DD + 1];

    const int  tid  = threadIdx.x;
    const bool isK  = (blockIdx.x >= 256);
    const int  blk  = isK ? (blockIdx.x - 256) : blockIdx.x;
    const int  rowBase = blk * 32;

    const float* __restrict__ X  = isK ? K  : Q;
    const float* __restrict__ W  = isK ? W2 : W1;
    const float* __restrict__ bb = isK ? b2 : b1;
    float* __restrict__ Out      = isK ? g_Wk : g_Wq;

    {
        const float4* src = (const float4*)W;
        float4* dst = (float4*)&Ws[0][0];
#pragma unroll
        for (int t = 0; t < 4; t++) dst[tid + t * 256] = src[tid + t * 256];
    }
#pragma unroll
    for (int t = 0; t < 8; t++) {
        int i = tid + t * 256;
        int r = i >> 6, c = i & 63;
        Xs[r][c] = X[(size_t)(rowBase + r) * DD + c];
    }
    __syncthreads();

    const int lane = tid & 31;
    const int eg   = tid >> 5;    // e-group: e = eg*8 + j

    double accp[4];               // packed f32 pairs
#pragma unroll
    for (int n = 0; n < 4; n++)
        accp[n] = f2x2(__ldg(&bb[eg * 8 + 2 * n]), __ldg(&bb[eg * 8 + 2 * n + 1]));

#pragma unroll
    for (int d = 0; d < DD; d++) {
        const float xv = Xs[lane][d];
        const double xvp = f2x2(xv, xv);
        const double2 wA = *(const double2*)&Ws[d][eg * 8];
        const double2 wB = *(const double2*)&Ws[d][eg * 8 + 4];
        accp[0] = fmx2(xvp, wA.x, accp[0]);
        accp[1] = fmx2(xvp, wA.y, accp[1]);
        accp[2] = fmx2(xvp, wB.x, accp[2]);
        accp[3] = fmx2(xvp, wB.y, accp[3]);
    }

    float acc[8];
#pragma unroll
    for (int n = 0; n < 4; n++) unpack2(accp[n], acc[2 * n], acc[2 * n + 1]);

    // Transform cols >= DMUFU: exp(2x) (Q) or -exp(2x) (K)
    {
        const float sgn = isK ? -1.0f : 1.0f;
#pragma unroll
        for (int j = 0; j < 8; j++)
            if (eg * 8 + j >= DMUFU) acc[j] = sgn * __expf(2.0f * acc[j]);
    }

    __syncthreads();
#pragma unroll
    for (int j = 0; j < 8; j++) Xs[lane][eg * 8 + j] = acc[j];
    __syncthreads();
#pragma unroll
    for (int t = 0; t < 8; t++) {
        int i = tid + t * 256;
        int r = i >> 6, c = i & 63;
        Out[(size_t)(rowBase + r) * DD + c] = Xs[r][c];     // coalesced
    }
}

// ---------------------------------------------------------------------------
// Main kernel: 128-thread blocks, tile 16q x 128k, 4x4 micro-tile per warp.
// Dispatch-balanced split (model T = max(8M, 2F+2A+2.7M)): 44 MUFU d's +
// 20 Halley-formula d's per (q,k).
//   10 fused iterations: 4 MUFU d's + 2 formula d's
//   + 1 MUFU-only tail iteration (d 40..43)
// Formula (zero MUFU): tanh(wq+wk) = 1 - 2/(1+eq*ek), 1 folds into bias;
//   nden = fma(eq,nek,-1); magic seed (ALU); Halley (err e->e^3);
//   acc = fma(r, -2v, acc).  5 F-ops + 2 A-ops per packed pair.
// ---------------------------------------------------------------------------
__global__ __launch_bounds__(128, 5) void attn_main_kernel(
    const float* __restrict__ Vv, const float* __restrict__ bV,
    float* __restrict__ out)
{
    __shared__ __align__(16) float wq_s[TQ][WPD];    // 16 x 68
    __shared__ __align__(16) float wk_s[TK][WPD];    // 128 x 68
    __shared__ __align__(16) float v_s[DD];          // v (d<44) or -2v (d>=44)

    const int bh    = blockIdx.z;
    const int qBase = blockIdx.y * TQ;
    const int kBase = blockIdx.x * TK;
    const int tid   = threadIdx.x;

    // ---- fill smem (coalesced global reads, padded stores) ----
    {
        const float* src = g_Wq + (size_t)(bh * LQ + qBase) * DD;
#pragma unroll
        for (int t = 0; t < 8; t++) {                 // 1024 = 16*64
            int i = tid + t * 128;
            wq_s[i >> 6][i & 63] = src[i];
        }
    }
    {
        const float* src = g_Wk + (size_t)(bh * LK + kBase) * DD;
#pragma unroll
        for (int t = 0; t < 64; t++) {                // 8192 = 128*64
            int i = tid + t * 128;
            wk_s[i >> 6][i & 63] = src[i];
        }
    }
    if (tid < DD) {
        float vv = Vv[tid];
        v_s[tid] = (tid < DMUFU) ? vv : (-2.0f * vv);
    }
    __syncthreads();

    const int ty = tid >> 5;          // warp id (0..3) -> q rows ty*4 .. ty*4+3
    const int tx = tid & 31;          // k lane; k = j*32 + tx

    double acc[4][4];
#pragma unroll
    for (int i = 0; i < 4; i++)
#pragma unroll
        for (int j = 0; j < 4; j++) acc[i][j] = 0.0;

    const double ONE  = f2x2(1.0f, 1.0f);
    const double MONE = f2x2(-1.0f, -1.0f);

    // ======== 10 fused iterations x (4 MUFU d's + 2 formula d's) ========
#pragma unroll 1
    for (int s2 = 0; s2 < 10; s2++) {
        const int cm = 4 * s2;            // MUFU cols    (0..39)
        const int cf = DMUFU + 2 * s2;    // formula cols (44..63)

        const double2 vm2 = *(const double2*)&v_s[cm];   // v pairs (MUFU)
        const double  m2v = *(const double*)&v_s[cf];    // -2v pair (formula)

        double2 wkm2[4];
        double  nek[4];
#pragma unroll
        for (int j = 0; j < 4; j++) {
            wkm2[j] = *(const double2*)&wk_s[j * 32 + tx][cm];  // LDS.128, CF
            nek[j]  = *(const double*)&wk_s[j * 32 + tx][cf];   // LDS.64, CF
        }

#pragma unroll
        for (int i = 0; i < 4; i++) {
            const double2 wqm2 = *(const double2*)&wq_s[ty * 4 + i][cm];  // broadcast
            const double  eq   = *(const double*)&wq_s[ty * 4 + i][cf];

#pragma unroll
            for (int j = 0; j < 4; j++) {
                // ---- formula: start reciprocal chain (zero MUFU) ----
                double nden = fmx2(eq, nek[j], MONE);      // -(1 + eq*ek)
                double r    = rcp_seed_from_neg(nden);     // ~1/den (ALU)

                // ---- MUFU path: 4 d's (tanh shadows Halley latency) ----
                double x0 = addx2(wqm2.x, wkm2[j].x);
                double x1 = addx2(wqm2.y, wkm2[j].y);
                float a0, a1, a2, a3;
                unpack2(x0, a0, a1);
                unpack2(x1, a2, a3);
                double t0 = f2x2(tanhapx(a0), tanhapx(a1));
                double t1 = f2x2(tanhapx(a2), tanhapx(a3));

                // ---- Halley refine + formula accumulate ----
                double h = fmx2(nden, r, ONE);             // residual e
                double t = fmx2(h, h, h);                  // e + e^2
                r = fmx2(r, t, r);                         // err -> e^3
                acc[i][j] = fmx2(r, m2v, acc[i][j]);       // += (-2v)/(1+p)

                // ---- MUFU accumulate ----
                acc[i][j] = fmx2(t0, vm2.x, acc[i][j]);
                acc[i][j] = fmx2(t1, vm2.y, acc[i][j]);
            }
        }
    }

    // ======== MUFU-only tail: cols 40..43 ========
    {
        const int cm = 40;
        const double2 vm2 = *(const double2*)&v_s[cm];

        double2 wkm2[4];
#pragma unroll
        for (int j = 0; j < 4; j++)
            wkm2[j] = *(const double2*)&wk_s[j * 32 + tx][cm];

#pragma unroll
        for (int i = 0; i < 4; i++) {
            const double2 wqm2 = *(const double2*)&wq_s[ty * 4 + i][cm];
#pragma unroll
            for (int j = 0; j < 4; j++) {
                double x0 = addx2(wqm2.x, wkm2[j].x);
                double x1 = addx2(wqm2.y, wkm2[j].y);
                float a0, a1, a2, a3;
                unpack2(x0, a0, a1);
                unpack2(x1, a2, a3);
                double t0 = f2x2(tanhapx(a0), tanhapx(a1));
                double t1 = f2x2(tanhapx(a2), tanhapx(a3));
                acc[i][j] = fmx2(t0, vm2.x, acc[i][j]);
                acc[i][j] = fmx2(t1, vm2.y, acc[i][j]);
            }
        }
    }

    // ---- epilogue: bias + sum(v) over formula d's (v = -0.5 * stored -2v) ----
    float vsum = 0.0f;
#pragma unroll
    for (int c = DMUFU; c < DD; c++) vsum += v_s[c];
    const float bv = bV[0] - 0.5f * vsum;

#pragma unroll
    for (int i = 0; i < 4; i++) {
        const size_t rowOff = (size_t)(bh * LQ + qBase + ty * 4 + i) * LK + kBase;
#pragma unroll
        for (int j = 0; j < 4; j++) {
            float lo, hi;
            unpack2(acc[i][j], lo, hi);
            out[rowOff + j * 32 + tx] = lo + hi + bv;      // coalesced
        }
    }
}

// ---------------------------------------------------------------------------
// Launch
// ---------------------------------------------------------------------------
extern "C" void kernel_launch(void* const* d_in, const int* in_sizes, int n_in,
                              void* d_out, int out_size)
{
    const float* Q  = (const float*)d_in[0];
    const float* K  = (const float*)d_in[1];
    const float* W1 = (const float*)d_in[2];
    const float* b1 = (const float*)d_in[3];
    const float* W2 = (const float*)d_in[4];
    const float* b2 = (const float*)d_in[5];
    const float* V  = (const float*)d_in[6];
    const float* bV = (const float*)d_in[7];
    float* out = (float*)d_out;

    proj_fused_kernel<<<512, 256>>>(Q, K, W1, b1, W2, b2);

    dim3 grid(LK / TK, LQ / TQ, BH);                  // 4 x 32 x 16 = 2048
    attn_main_kernel<<<grid, 128>>>(V, bV, out);
}

// round 16
// speedup vs baseline: 1.0986x; 1.0309x over previous
#include <cuda_runtime.h>

#define BH    16
#define LQ    512
#define LK    512
#define DD    64
#define DMUFU 32     // d in [0,32): raw values, MUFU tanh path
#define TQ    16
#define TK    128
#define WPD   68     // smem row stride in floats: 272B, 16B-aligned, LDS.128 conflict-free

// Projected tensors, f32 [row][64]:
//   g_Wq: cols 0..31 = raw wq,  cols 32..63 = exp(2*wq)
//   g_Wk: cols 0..31 = raw wk,  cols 32..63 = -exp(2*wk)
__device__ float g_Wq[BH * LQ * DD];
__device__ float g_Wk[BH * LK * DD];

// ---------------------------------------------------------------------------
// Helpers
// ---------------------------------------------------------------------------
__device__ __forceinline__ float tanhapx(float x) {
    float y; asm("tanh.approx.f32 %0, %1;" : "=f"(y) : "f"(x)); return y;
}
__device__ __forceinline__ double f2x2(float lo, float hi) {
    double r; asm("mov.b64 %0, {%1, %2};" : "=d"(r) : "f"(lo), "f"(hi)); return r;
}
__device__ __forceinline__ void unpack2(double p, float& lo, float& hi) {
    asm("mov.b64 {%0, %1}, %2;" : "=f"(lo), "=f"(hi) : "d"(p));
}
__device__ __forceinline__ double addx2(double a, double b) {
    double r; asm("add.rn.f32x2 %0, %1, %2;" : "=d"(r) : "d"(a), "d"(b)); return r;
}
__device__ __forceinline__ double fmx2(double a, double b, double c) {
    double r; asm("fma.rn.f32x2 %0, %1, %2, %3;" : "=d"(r) : "d"(a), "d"(b), "d"(c)); return r;
}
// Reciprocal seed of +D from bits of (-D): 0xFEF311C3 - bits(-D). D > 0.
__device__ __forceinline__ double rcp_seed_from_neg(double dn) {
    unsigned lo, hi;
    asm("mov.b64 {%0, %1}, %2;" : "=r"(lo), "=r"(hi) : "d"(dn));
    lo = 0xFEF311C3u - lo;
    hi = 0xFEF311C3u - hi;
    double r; asm("mov.b64 %0, {%1, %2};" : "=d"(r) : "r"(lo), "r"(hi)); return r;
}

// ---------------------------------------------------------------------------
// Fused projection kernel (fp32, packed f32x2 inner loop).
//   blocks [0,256):    Wq = Q*W1 + b1 ; cols 32..63 -> exp(2x)
//   blocks [256,512):  Wk = K*W2 + b2 ; cols 32..63 -> -exp(2x)
// ---------------------------------------------------------------------------
__global__ __launch_bounds__(256) void proj_fused_kernel(
    const float* __restrict__ Q, const float* __restrict__ K,
    const float* __restrict__ W1, const float* __restrict__ b1,
    const float* __restrict__ W2, const float* __restrict__ b2)
{
    __shared__ __align__(16) float Ws[DD][DD];
    __shared__ float Xs[32][DD + 1];

    const int  tid  = threadIdx.x;
    const bool isK  = (blockIdx.x >= 256);
    const int  blk  = isK ? (blockIdx.x - 256) : blockIdx.x;
    const int  rowBase = blk * 32;

    const float* __restrict__ X  = isK ? K  : Q;
    const float* __restrict__ W  = isK ? W2 : W1;
    const float* __restrict__ bb = isK ? b2 : b1;
    float* __restrict__ Out      = isK ? g_Wk : g_Wq;

    {
        const float4* src = (const float4*)W;
        float4* dst = (float4*)&Ws[0][0];
#pragma unroll
        for (int t = 0; t < 4; t++) dst[tid + t * 256] = src[tid + t * 256];
    }
#pragma unroll
    for (int t = 0; t < 8; t++) {
        int i = tid + t * 256;
        int r = i >> 6, c = i & 63;
        Xs[r][c] = X[(size_t)(rowBase + r) * DD + c];
    }
    __syncthreads();

    const int lane = tid & 31;
    const int eg   = tid >> 5;    // e-group: e = eg*8 + j

    double accp[4];               // packed f32 pairs
#pragma unroll
    for (int n = 0; n < 4; n++)
        accp[n] = f2x2(__ldg(&bb[eg * 8 + 2 * n]), __ldg(&bb[eg * 8 + 2 * n + 1]));

#pragma unroll
    for (int d = 0; d < DD; d++) {
        const float xv = Xs[lane][d];
        const double xvp = f2x2(xv, xv);
        const double2 wA = *(const double2*)&Ws[d][eg * 8];
        const double2 wB = *(const double2*)&Ws[d][eg * 8 + 4];
        accp[0] = fmx2(xvp, wA.x, accp[0]);
        accp[1] = fmx2(xvp, wA.y, accp[1]);
        accp[2] = fmx2(xvp, wB.x, accp[2]);
        accp[3] = fmx2(xvp, wB.y, accp[3]);
    }

    float acc[8];
#pragma unroll
    for (int n = 0; n < 4; n++) unpack2(accp[n], acc[2 * n], acc[2 * n + 1]);

    // Transform cols >= DMUFU: exp(2x) (Q) or -exp(2x) (K)
    if (eg >= 4) {
        const float sgn = isK ? -1.0f : 1.0f;
#pragma unroll
        for (int j = 0; j < 8; j++) acc[j] = sgn * __expf(2.0f * acc[j]);
    }

    __syncthreads();
#pragma unroll
    for (int j = 0; j < 8; j++) Xs[lane][eg * 8 + j] = acc[j];
    __syncthreads();
#pragma unroll
    for (int t = 0; t < 8; t++) {
        int i = tid + t * 256;
        int r = i >> 6, c = i & 63;
        Out[(size_t)(rowBase + r) * DD + c] = Xs[r][c];     // coalesced
    }
}

// ---------------------------------------------------------------------------
// Main kernel: 128-thread blocks, tile 16q x 128k, 4x4 micro-tile per warp.
// R13 structure (validated 89.8K cyc, dispatch-bound) with Halley instead of
// Newton x2 on the formula path (-16 F-ops/qk -> predicted 82.9K cyc).
// 8 fused iterations, each: 4 MUFU d's + 4 formula d's per (q,k):
//   MUFU:    addx2 -> tanh.approx.f32 x2 -> packed fma          (d 0..31)
//   formula: tanh(wq+wk) = 1 - 2/(1 + eq*ek); the 1 folds into the bias.
//            nden = fma(eq,nek,-1); magic seed (ALU); Halley (err e->e^3);
//            acc += r*(-2v)  -> 5 F-ops + 2 A-ops per packed pair, zero MUFU.
// ---------------------------------------------------------------------------
__global__ __launch_bounds__(128, 5) void attn_main_kernel(
    const float* __restrict__ Vv, const float* __restrict__ bV,
    float* __restrict__ out)
{
    __shared__ __align__(16) float wq_s[TQ][WPD];    // 16 x 68
    __shared__ __align__(16) float wk_s[TK][WPD];    // 128 x 68
    __shared__ __align__(16) float v_s[DD];          // v (d<32) or -2v (d>=32)

    const int bh    = blockIdx.z;
    const int qBase = blockIdx.y * TQ;
    const int kBase = blockIdx.x * TK;
    const int tid   = threadIdx.x;

    // ---- fill smem (coalesced global reads, padded stores) ----
    {
        const float* src = g_Wq + (size_t)(bh * LQ + qBase) * DD;
#pragma unroll
        for (int t = 0; t < 8; t++) {                 // 1024 = 16*64
            int i = tid + t * 128;
            wq_s[i >> 6][i & 63] = src[i];
        }
    }
    {
        const float* src = g_Wk + (size_t)(bh * LK + kBase) * DD;
#pragma unroll
        for (int t = 0; t < 64; t++) {                // 8192 = 128*64
            int i = tid + t * 128;
            wk_s[i >> 6][i & 63] = src[i];
        }
    }
    if (tid < DD) {
        float vv = Vv[tid];
        v_s[tid] = (tid < DMUFU) ? vv : (-2.0f * vv);
    }
    __syncthreads();

    const int ty = tid >> 5;          // warp id (0..3) -> q rows ty*4 .. ty*4+3
    const int tx = tid & 31;          // k lane; k = j*32 + tx

    double acc[4][4];
#pragma unroll
    for (int i = 0; i < 4; i++)
#pragma unroll
        for (int j = 0; j < 4; j++) acc[i][j] = 0.0;

    const double ONE  = f2x2(1.0f, 1.0f);
    const double MONE = f2x2(-1.0f, -1.0f);

    // ======== 8 fused iterations x (4 MUFU d's + 4 formula d's) ========
#pragma unroll 1
    for (int s2 = 0; s2 < 8; s2++) {
        const int cm = 4 * s2;            // MUFU cols    (0..31)
        const int cf = DMUFU + 4 * s2;    // formula cols (32..63)

        const double2 vm2  = *(const double2*)&v_s[cm];   // v pairs
        const double2 m2v2 = *(const double2*)&v_s[cf];   // -2v pairs

        double2 wkm2[4], wkf2[4];
#pragma unroll
        for (int j = 0; j < 4; j++) {
            wkm2[j] = *(const double2*)&wk_s[j * 32 + tx][cm];   // LDS.128, stride 68: CF
            wkf2[j] = *(const double2*)&wk_s[j * 32 + tx][cf];   // nek pairs
        }

#pragma unroll
        for (int i = 0; i < 4; i++) {
            const double2 wqm2 = *(const double2*)&wq_s[ty * 4 + i][cm];  // broadcast
            const double2 eq2  = *(const double2*)&wq_s[ty * 4 + i][cf];

#pragma unroll
            for (int j = 0; j < 4; j++) {
                // ---- formula: start reciprocal chains (zero MUFU) ----
                double nden0 = fmx2(eq2.x, wkf2[j].x, MONE);   // -(1 + eq*ek)
                double nden1 = fmx2(eq2.y, wkf2[j].y, MONE);
                double r0    = rcp_seed_from_neg(nden0);       // ~1/den (ALU)
                double r1    = rcp_seed_from_neg(nden1);

                // ---- MUFU path: 4 d's (tanh shadows Halley latency) ----
                double x0 = addx2(wqm2.x, wkm2[j].x);
                double x1 = addx2(wqm2.y, wkm2[j].y);
                float a0, a1, a2, a3;
                unpack2(x0, a0, a1);
                unpack2(x1, a2, a3);
                double t0 = f2x2(tanhapx(a0), tanhapx(a1));
                double t1 = f2x2(tanhapx(a2), tanhapx(a3));

                // ---- Halley refine + formula accumulate ----
                double h0 = fmx2(nden0, r0, ONE);              // residual e
                double h1 = fmx2(nden1, r1, ONE);
                double u0 = fmx2(h0, h0, h0);                  // e + e^2
                double u1 = fmx2(h1, h1, h1);
                r0 = fmx2(r0, u0, r0);                         // err -> e^3
                r1 = fmx2(r1, u1, r1);
                acc[i][j] = fmx2(r0, m2v2.x, acc[i][j]);       // += (-2v)/(1+p)
                acc[i][j] = fmx2(r1, m2v2.y, acc[i][j]);

                // ---- MUFU accumulate ----
                acc[i][j] = fmx2(t0, vm2.x, acc[i][j]);
                acc[i][j] = fmx2(t1, vm2.y, acc[i][j]);
            }
        }
    }

    // ---- epilogue: bias + sum(v) over formula d's (v = -0.5 * stored -2v) ----
    float vsum = 0.0f;
#pragma unroll
    for (int c = DMUFU; c < DD; c++) vsum += v_s[c];
    const float bv = bV[0] - 0.5f * vsum;

#pragma unroll
    for (int i = 0; i < 4; i++) {
        const size_t rowOff = (size_t)(bh * LQ + qBase + ty * 4 + i) * LK + kBase;
#pragma unroll
        for (int j = 0; j < 4; j++) {
            float lo, hi;
            unpack2(acc[i][j], lo, hi);
            out[rowOff + j * 32 + tx] = lo + hi + bv;      // coalesced
        }
    }
}

// ---------------------------------------------------------------------------
// Launch
// ---------------------------------------------------------------------------
extern "C" void kernel_launch(void* const* d_in, const int* in_sizes, int n_in,
                              void* d_out, int out_size)
{
    const float* Q  = (const float*)d_in[0];
    const float* K  = (const float*)d_in[1];
    const float* W1 = (const float*)d_in[2];
    const float* b1 = (const float*)d_in[3];
    const float* W2 = (const float*)d_in[4];
    const float* b2 = (const float*)d_in[5];
    const float* V  = (const float*)d_in[6];
    const float* bV = (const float*)d_in[7];
    float* out = (float*)d_out;

    proj_fused_kernel<<<512, 256>>>(Q, K, W1, b1, W2, b2);

    dim3 grid(LK / TK, LQ / TQ, BH);                  // 4 x 32 x 16 = 2048
    attn_main_kernel<<<grid, 128>>>(V, bV, out);
}

// round 17
// speedup vs baseline: 1.1869x; 1.0804x over previous
#include <cuda_runtime.h>

#define BH    16
#define LQ    512
#define LK    512
#define DD    64
#define DMUFU 32     // d in [0,32): raw values, MUFU tanh path
#define TQ    16
#define TK    128
#define WPD   66     // smem row stride in floats: 264B, 8B-aligned rows,
                     // LDS.64 conflict-free (bank = (2tx+c) mod 32, full coverage)

// Projected tensors, f32 [row][64]:
//   g_Wq: cols 0..31 = raw wq,  cols 32..63 = exp(2*wq)
//   g_Wk: cols 0..31 = raw wk,  cols 32..63 = -exp(2*wk)
__device__ float g_Wq[BH * LQ * DD];
__device__ float g_Wk[BH * LK * DD];

// ---------------------------------------------------------------------------
// Helpers
// ---------------------------------------------------------------------------
__device__ __forceinline__ float tanhapx(float x) {
    float y; asm("tanh.approx.f32 %0, %1;" : "=f"(y) : "f"(x)); return y;
}
__device__ __forceinline__ double f2x2(float lo, float hi) {
    double r; asm("mov.b64 %0, {%1, %2};" : "=d"(r) : "f"(lo), "f"(hi)); return r;
}
__device__ __forceinline__ void unpack2(double p, float& lo, float& hi) {
    asm("mov.b64 {%0, %1}, %2;" : "=f"(lo), "=f"(hi) : "d"(p));
}
__device__ __forceinline__ double addx2(double a, double b) {
    double r; asm("add.rn.f32x2 %0, %1, %2;" : "=d"(r) : "d"(a), "d"(b)); return r;
}
__device__ __forceinline__ double fmx2(double a, double b, double c) {
    double r; asm("fma.rn.f32x2 %0, %1, %2, %3;" : "=d"(r) : "d"(a), "d"(b), "d"(c)); return r;
}
// Reciprocal seed of +D from bits of (-D): 0xFEF311C3 - bits(-D). D > 0.
__device__ __forceinline__ double rcp_seed_from_neg(double dn) {
    unsigned lo, hi;
    asm("mov.b64 {%0, %1}, %2;" : "=r"(lo), "=r"(hi) : "d"(dn));
    lo = 0xFEF311C3u - lo;
    hi = 0xFEF311C3u - hi;
    double r; asm("mov.b64 %0, {%1, %2};" : "=d"(r) : "r"(lo), "r"(hi)); return r;
}

// ---------------------------------------------------------------------------
// Fused projection kernel (fp32, packed f32x2 inner loop).
//   blocks [0,256):    Wq = Q*W1 + b1 ; cols 32..63 -> exp(2x)
//   blocks [256,512):  Wk = K*W2 + b2 ; cols 32..63 -> -exp(2x)
// ---------------------------------------------------------------------------
__global__ __launch_bounds__(256) void proj_fused_kernel(
    const float* __restrict__ Q, const float* __restrict__ K,
    const float* __restrict__ W1, const float* __restrict__ b1,
    const float* __restrict__ W2, const float* __restrict__ b2)
{
    __shared__ __align__(16) float Ws[DD][DD];
    __shared__ float Xs[32][DD + 1];

    const int  tid  = threadIdx.x;
    const bool isK  = (blockIdx.x >= 256);
    const int  blk  = isK ? (blockIdx.x - 256) : blockIdx.x;
    const int  rowBase = blk * 32;

    const float* __restrict__ X  = isK ? K  : Q;
    const float* __restrict__ W  = isK ? W2 : W1;
    const float* __restrict__ bb = isK ? b2 : b1;
    float* __restrict__ Out      = isK ? g_Wk : g_Wq;

    {
        const float4* src = (const float4*)W;
        float4* dst = (float4*)&Ws[0][0];
#pragma unroll
        for (int t = 0; t < 4; t++) dst[tid + t * 256] = src[tid + t * 256];
    }
#pragma unroll
    for (int t = 0; t < 8; t++) {
        int i = tid + t * 256;
        int r = i >> 6, c = i & 63;
        Xs[r][c] = X[(size_t)(rowBase + r) * DD + c];
    }
    __syncthreads();

    const int lane = tid & 31;
    const int eg   = tid >> 5;    // e-group: e = eg*8 + j

    double accp[4];               // packed f32 pairs
#pragma unroll
    for (int n = 0; n < 4; n++)
        accp[n] = f2x2(__ldg(&bb[eg * 8 + 2 * n]), __ldg(&bb[eg * 8 + 2 * n + 1]));

#pragma unroll
    for (int d = 0; d < DD; d++) {
        const float xv = Xs[lane][d];
        const double xvp = f2x2(xv, xv);
        const double2 wA = *(const double2*)&Ws[d][eg * 8];
        const double2 wB = *(const double2*)&Ws[d][eg * 8 + 4];
        accp[0] = fmx2(xvp, wA.x, accp[0]);
        accp[1] = fmx2(xvp, wA.y, accp[1]);
        accp[2] = fmx2(xvp, wB.x, accp[2]);
        accp[3] = fmx2(xvp, wB.y, accp[3]);
    }

    float acc[8];
#pragma unroll
    for (int n = 0; n < 4; n++) unpack2(accp[n], acc[2 * n], acc[2 * n + 1]);

    // Transform cols >= DMUFU: exp(2x) (Q) or -exp(2x) (K)
    if (eg >= 4) {
        const float sgn = isK ? -1.0f : 1.0f;
#pragma unroll
        for (int j = 0; j < 8; j++) acc[j] = sgn * __expf(2.0f * acc[j]);
    }

    __syncthreads();
#pragma unroll
    for (int j = 0; j < 8; j++) Xs[lane][eg * 8 + j] = acc[j];
    __syncthreads();
#pragma unroll
    for (int t = 0; t < 8; t++) {
        int i = tid + t * 256;
        int r = i >> 6, c = i & 63;
        Out[(size_t)(rowBase + r) * DD + c] = Xs[r][c];     // coalesced
    }
}

// ---------------------------------------------------------------------------
// Main kernel: 128-thread blocks, tile 16q x 128k, 4x4 micro-tile per warp,
// 6 CTAs/SM (smem 38.3KB <= 38.9KB budget, 85-reg cap). Same math as R16:
//   MUFU:    addx2 -> tanh.approx.f32 x2 -> packed fma          (d 0..31)
//   formula: tanh(wq+wk) = 1 - 2/(1 + eq*ek); 1 folds into bias.
//            nden = fma(eq,nek,-1); magic seed (ALU); Halley (err e^3);
//            acc += r*(-2v)  (zero MUFU)                        (d 32..63)
// j-loop split into 2 halves of 2 k-groups to fit the 85-reg cap.
// ---------------------------------------------------------------------------
__global__ __launch_bounds__(128, 6) void attn_main_kernel(
    const float* __restrict__ Vv, const float* __restrict__ bV,
    float* __restrict__ out)
{
    __shared__ __align__(16) float wq_s[TQ][WPD];    // 16 x 66
    __shared__ __align__(16) float wk_s[TK][WPD];    // 128 x 66
    __shared__ __align__(16) float v_s[DD];          // v (d<32) or -2v (d>=32)

    const int bh    = blockIdx.z;
    const int qBase = blockIdx.y * TQ;
    const int kBase = blockIdx.x * TK;
    const int tid   = threadIdx.x;

    // ---- fill smem (coalesced global reads, padded stores) ----
    {
        const float* src = g_Wq + (size_t)(bh * LQ + qBase) * DD;
#pragma unroll
        for (int t = 0; t < 8; t++) {                 // 1024 = 16*64
            int i = tid + t * 128;
            wq_s[i >> 6][i & 63] = src[i];
        }
    }
    {
        const float* src = g_Wk + (size_t)(bh * LK + kBase) * DD;
#pragma unroll
        for (int t = 0; t < 64; t++) {                // 8192 = 128*64
            int i = tid + t * 128;
            wk_s[i >> 6][i & 63] = src[i];
        }
    }
    if (tid < DD) {
        float vv = Vv[tid];
        v_s[tid] = (tid < DMUFU) ? vv : (-2.0f * vv);
    }
    __syncthreads();

    const int ty = tid >> 5;          // warp id (0..3) -> q rows ty*4 .. ty*4+3
    const int tx = tid & 31;          // k lane; k = j*32 + tx

    double acc[4][4];
#pragma unroll
    for (int i = 0; i < 4; i++)
#pragma unroll
        for (int j = 0; j < 4; j++) acc[i][j] = 0.0;

    const double ONE  = f2x2(1.0f, 1.0f);
    const double MONE = f2x2(-1.0f, -1.0f);

    // ======== 8 iterations x (4 MUFU d's + 4 formula d's), j in 2 halves ====
#pragma unroll 1
    for (int s2 = 0; s2 < 8; s2++) {
        const int cm = 4 * s2;            // MUFU cols    (0..31)
        const int cf = DMUFU + 4 * s2;    // formula cols (32..63)

        const double2 vm2  = *(const double2*)&v_s[cm];   // v pairs (16B-aligned)
        const double2 m2v2 = *(const double2*)&v_s[cf];   // -2v pairs

#pragma unroll
        for (int jh = 0; jh < 2; jh++) {
            // wk operands for 2 k-groups (LDS.64, stride 66: conflict-free)
            double wkm0[2], wkm1[2], nek0[2], nek1[2];
#pragma unroll
            for (int j2 = 0; j2 < 2; j2++) {
                const float* row = &wk_s[(jh * 2 + j2) * 32 + tx][0];
                wkm0[j2] = *(const double*)&row[cm];
                wkm1[j2] = *(const double*)&row[cm + 2];
                nek0[j2] = *(const double*)&row[cf];
                nek1[j2] = *(const double*)&row[cf + 2];
            }

#pragma unroll
            for (int i = 0; i < 4; i++) {
                const float* qrow = &wq_s[ty * 4 + i][0];    // broadcast reads
                const double wqm0 = *(const double*)&qrow[cm];
                const double wqm1 = *(const double*)&qrow[cm + 2];
                const double eq0  = *(const double*)&qrow[cf];
                const double eq1  = *(const double*)&qrow[cf + 2];

#pragma unroll
                for (int j2 = 0; j2 < 2; j2++) {
                    const int j = jh * 2 + j2;

                    // ---- formula: start reciprocal chains (zero MUFU) ----
                    double nden0 = fmx2(eq0, nek0[j2], MONE);   // -(1 + eq*ek)
                    double nden1 = fmx2(eq1, nek1[j2], MONE);
                    double r0    = rcp_seed_from_neg(nden0);    // ~1/den (ALU)
                    double r1    = rcp_seed_from_neg(nden1);

                    // ---- MUFU path: 4 d's (tanh shadows Halley latency) ----
                    double x0 = addx2(wqm0, wkm0[j2]);
                    double x1 = addx2(wqm1, wkm1[j2]);
                    float a0, a1, a2, a3;
                    unpack2(x0, a0, a1);
                    unpack2(x1, a2, a3);
                    double t0 = f2x2(tanhapx(a0), tanhapx(a1));
                    double t1 = f2x2(tanhapx(a2), tanhapx(a3));

                    // ---- Halley refine + formula accumulate ----
                    double h0 = fmx2(nden0, r0, ONE);           // residual e
                    double h1 = fmx2(nden1, r1, ONE);
                    double u0 = fmx2(h0, h0, h0);               // e + e^2
                    double u1 = fmx2(h1, h1, h1);
                    r0 = fmx2(r0, u0, r0);                      // err -> e^3
                    r1 = fmx2(r1, u1, r1);
                    acc[i][j] = fmx2(r0, m2v2.x, acc[i][j]);    // += (-2v)/(1+p)
                    acc[i][j] = fmx2(r1, m2v2.y, acc[i][j]);

                    // ---- MUFU accumulate ----
                    acc[i][j] = fmx2(t0, vm2.x, acc[i][j]);
                    acc[i][j] = fmx2(t1, vm2.y, acc[i][j]);
                }
            }
        }
    }

    // ---- epilogue: bias + sum(v) over formula d's (v = -0.5 * stored -2v) ----
    float vsum = 0.0f;
#pragma unroll
    for (int c = DMUFU; c < DD; c++) vsum += v_s[c];
    const float bv = bV[0] - 0.5f * vsum;

#pragma unroll
    for (int i = 0; i < 4; i++) {
        const size_t rowOff = (size_t)(bh * LQ + qBase + ty * 4 + i) * LK + kBase;
#pragma unroll
        for (int j = 0; j < 4; j++) {
            float lo, hi;
            unpack2(acc[i][j], lo, hi);
            out[rowOff + j * 32 + tx] = lo + hi + bv;      // coalesced
        }
    }
}

// ---------------------------------------------------------------------------
// Launch
// ---------------------------------------------------------------------------
extern "C" void kernel_launch(void* const* d_in, const int* in_sizes, int n_in,
                              void* d_out, int out_size)
{
    const float* Q  = (const float*)d_in[0];
    const float* K  = (const float*)d_in[1];
    const float* W1 = (const float*)d_in[2];
    const float* b1 = (const float*)d_in[3];
    const float* W2 = (const float*)d_in[4];
    const float* b2 = (const float*)d_in[5];
    const float* V  = (const float*)d_in[6];
    const float* bV = (const float*)d_in[7];
    float* out = (float*)d_out;

    proj_fused_kernel<<<512, 256>>>(Q, K, W1, b1, W2, b2);

    dim3 grid(LK / TK, LQ / TQ, BH);                  // 4 x 32 x 16 = 2048
    attn_main_kernel<<<grid, 128>>>(V, bV, out);
}